// round 3
// baseline (speedup 1.0000x reference)
#include <cuda_runtime.h>
#include <cuda_bf16.h>

#define FULL_MASK 0xFFFFFFFFu
#define ROWS_PER_BLOCK 32
// V floats needed per block: 32 rows * 33 + alignment slack (<=3) -> 1060
#define SV_FLOATS 1060

// 8 lanes per row, 4 rows per warp, 32 rows per 256-thread block.
// V staged through smem with aligned float4 loads.
__global__ __launch_bounds__(256, 8)
void pwq_coupling_kernel(const float* __restrict__ x_b,
                         const float* __restrict__ W,
                         const float* __restrict__ V,
                         float* __restrict__ out,   // [0:n)=z, [n:2n)=log_det
                         int n)
{
    __shared__ float sV[SV_FLOATS];

    const int tid  = threadIdx.x;
    const int lane = tid & 31;
    const int t    = lane & 7;                 // sublane within 8-lane segment
    const int r0   = blockIdx.x * ROWS_PER_BLOCK;

    // ---- cooperative V staging: aligned float4 loads ----
    const long long baseFloat    = (long long)r0 * 33;
    const long long alignedBase  = baseFloat & ~3LL;
    const int       off          = (int)(baseFloat - alignedBase);   // 0..3
    const long long totalV       = (long long)n * 33;                // divisible by 4
    const int needFloats = off + ROWS_PER_BLOCK * 33;                // <= 1059
    const int nF4 = (needFloats + 3) >> 2;                           // <= 265
    const float4* __restrict__ Vq = (const float4*)(V + alignedBase);
    #pragma unroll 2
    for (int i = tid; i < nF4; i += 256) {
        if (alignedBase + 4LL * i + 4 <= totalV) {
            const float4 q = Vq[i];
            *(float4*)(sV + 4 * i) = q;
        }
    }

    const int rowLocal = ((tid >> 5) << 2) + ((lane >> 3));  // warp*4 + subrow
    const int row = r0 + rowLocal;

    // W load + x load overlap the staging
    float4 w4 = make_float4(0.f, 0.f, 0.f, 0.f);
    float x = 0.0f;
    if (row < n) {
        w4 = *(const float4*)(W + (size_t)row * 32 + t * 4);  // 16B aligned
        x  = x_b[row];                                        // broadcast in segment
    }
    __syncthreads();
    if (row >= n) return;

    // ---- 5 consecutive vertices from smem (conflict-free) ----
    const float* sv = sV + off + rowLocal * 33 + t * 4;
    const float v0 = sv[0];
    const float v1 = sv[1];
    const float v2 = sv[2];
    const float v3 = sv[3];
    const float v4 = sv[4];

    // ---- local trapezoid areas ----
    const float a0 = 0.5f * (v0 + v1) * w4.x;
    const float a1 = 0.5f * (v1 + v2) * w4.y;
    const float a2 = 0.5f * (v2 + v3) * w4.z;
    const float a3 = 0.5f * (v3 + v4) * w4.w;

    // ---- local inclusive prefixes (4 elems) ----
    const float lw1 = w4.x + w4.y;
    const float lw2 = lw1 + w4.z;
    const float lw3 = lw2 + w4.w;
    const float la1 = a0 + a1;
    const float la2 = la1 + a2;
    const float la3 = la2 + a3;

    // ---- segmented 8-lane scan of segment totals ----
    float cw = lw3, ca = la3;
    #pragma unroll
    for (int d = 1; d < 8; d <<= 1) {
        const float tw = __shfl_up_sync(FULL_MASK, cw, d, 8);
        const float ta = __shfl_up_sync(FULL_MASK, ca, d, 8);
        if (t >= d) { cw += tw; ca += ta; }
    }
    const float bw = cw - lw3;                 // left edge of bin 4t
    const float ba = ca - la3;                 // CDF at left edge of bin 4t

    // inclusive W-cumsum at this lane's 4 bins = edges[4t+1 .. 4t+4]
    const float cw0 = bw + w4.x;
    const float cw1 = bw + lw1;
    const float cw2 = bw + lw2;
    const float cw3 = bw + lw3;

    // ---- bin search: count interior edges <= val across the row ----
    const float val = fminf(fmaxf(x, 0.0f), 0.9999f);
    int cnt = (int)(val >= cw0) + (int)(val >= cw1)
            + (int)(val >= cw2) + (int)(val >= cw3);
    #pragma unroll
    for (int d = 1; d < 8; d <<= 1)
        cnt += __shfl_xor_sync(FULL_MASK, cnt, d, 8);
    const int bin = min(cnt, 31);
    const int o = bin >> 2;                    // owner sublane
    const int j = bin & 3;                     // local index within owner

    // ---- each lane selects its local j-th candidate ----
    const bool j1 = (j & 1), j2 = (j & 2);
    const float e_sel  = j2 ? (j1 ? cw2 : cw1) : (j1 ? cw0 : bw);
    const float p1 = ba + a0, p2 = ba + la1, p3 = ba + la2;
    const float p_sel  = j2 ? (j1 ? p3 : p2) : (j1 ? p1 : ba);
    const float w_sel  = j2 ? (j1 ? w4.w : w4.z) : (j1 ? w4.y : w4.x);
    const float vb_sel = j2 ? (j1 ? v3 : v2) : (j1 ? v1 : v0);
    const float v1_sel = j2 ? (j1 ? v4 : v3) : (j1 ? v2 : v1);

    // ---- broadcast from the owning sublane ----
    const float w_b    = __shfl_sync(FULL_MASK, w_sel,  o, 8);
    const float v_b    = __shfl_sync(FULL_MASK, vb_sel, o, 8);
    const float v_b1   = __shfl_sync(FULL_MASK, v1_sel, o, 8);
    const float edge_b = __shfl_sync(FULL_MASK, e_sel,  o, 8);
    const float apre_b = __shfl_sync(FULL_MASK, p_sel,  o, 8);

    if (t == 0) {
        const float alpha = __fdividef(val - edge_b, w_b + 1e-8f);
        const float dv    = v_b1 - v_b;
        const float z     = apre_b + alpha * w_b * (v_b + 0.5f * alpha * dv);
        out[row]     = z;
        out[n + row] = __logf(v_b + alpha * dv + 1e-8f);
    }
}

extern "C" void kernel_launch(void* const* d_in, const int* in_sizes, int n_in,
                              void* d_out, int out_size)
{
    const float* x_b = (const float*)d_in[0];
    const float* W   = (const float*)d_in[1];
    const float* V   = (const float*)d_in[2];
    float* out = (float*)d_out;

    const int n = in_sizes[0];
    const int blocks = (n + ROWS_PER_BLOCK - 1) / ROWS_PER_BLOCK;
    pwq_coupling_kernel<<<blocks, 256>>>(x_b, W, V, out, n);
}

// round 4
// speedup vs baseline: 1.5020x; 1.5020x over previous
#include <cuda_runtime.h>
#include <cuda_bf16.h>

#define FULL_MASK 0xFFFFFFFFu

// 4 lanes per row (8 bins each), 8 rows per warp.
// Owner-lane finalization: no broadcast shuffles.
__global__ __launch_bounds__(256)
void pwq_coupling_kernel(const float* __restrict__ x_b,
                         const float* __restrict__ W,
                         const float* __restrict__ V,
                         float* __restrict__ out,   // [0:n)=z, [n:2n)=log_det
                         int n)
{
    const int lane = threadIdx.x & 31;
    const int t    = lane & 3;                 // sublane within 4-lane segment
    const int warpGlobal = (blockIdx.x * blockDim.x + threadIdx.x) >> 5;
    const int row = warpGlobal * 8 + (lane >> 2);
    if (row >= n) return;                      // n % 8 == 0 -> warp-uniform

    // ---- loads, issued up front for MLP ----
    const float* Wrow = W + (size_t)row * 32 + t * 8;
    const float4 wa = *(const float4*)(Wrow);      // bins 8t..8t+3
    const float4 wb = *(const float4*)(Wrow + 4);  // bins 8t+4..8t+7
    const float* Vrow = V + (size_t)row * 33 + t * 8;
    const float v0 = Vrow[0];
    const float v1 = Vrow[1];
    const float v2 = Vrow[2];
    const float v3 = Vrow[3];
    const float v4 = Vrow[4];
    const float v5 = Vrow[5];
    const float v6 = Vrow[6];
    const float v7 = Vrow[7];
    const float x  = x_b[row];                 // 4 lanes same addr -> broadcast

    // 9th vertex: next sublane's v0; sublane 3 loads V[row,32]
    float v8 = __shfl_down_sync(FULL_MASK, v0, 1, 4);
    if (t == 3) v8 = Vrow[8];

    // ---- trapezoid areas ----
    const float a0 = 0.5f * (v0 + v1) * wa.x;
    const float a1 = 0.5f * (v1 + v2) * wa.y;
    const float a2 = 0.5f * (v2 + v3) * wa.z;
    const float a3 = 0.5f * (v3 + v4) * wa.w;
    const float a4 = 0.5f * (v4 + v5) * wb.x;
    const float a5 = 0.5f * (v5 + v6) * wb.y;
    const float a6 = 0.5f * (v6 + v7) * wb.z;
    const float a7 = 0.5f * (v7 + v8) * wb.w;

    // ---- local inclusive prefixes (8 elems) ----
    const float pw1 = wa.x;
    const float pw2 = pw1 + wa.y;
    const float pw3 = pw2 + wa.z;
    const float pw4 = pw3 + wa.w;
    const float pw5 = pw4 + wb.x;
    const float pw6 = pw5 + wb.y;
    const float pw7 = pw6 + wb.z;
    const float pw8 = pw7 + wb.w;
    const float pa1 = a0;
    const float pa2 = pa1 + a1;
    const float pa3 = pa2 + a2;
    const float pa4 = pa3 + a3;
    const float pa5 = pa4 + a4;
    const float pa6 = pa5 + a5;
    const float pa7 = pa6 + a6;
    const float pa8 = pa7 + a7;

    // ---- segmented 4-lane scan of segment totals ----
    float cw = pw8, ca = pa8;
    #pragma unroll
    for (int d = 1; d < 4; d <<= 1) {
        const float tw = __shfl_up_sync(FULL_MASK, cw, d, 4);
        const float ta = __shfl_up_sync(FULL_MASK, ca, d, 4);
        if (t >= d) { cw += tw; ca += ta; }
    }
    const float bw = cw - pw8;                 // left edge of bin 8t
    const float ba = ca - pa8;                 // CDF at left edge of bin 8t

    // ---- bin search: count interior edges <= val across the row ----
    const float val = fminf(fmaxf(x, 0.0f), 0.9999f);
    const float vb  = val - bw;                // compare in segment-local coords
    int cnt = (int)(vb >= pw1) + (int)(vb >= pw2)
            + (int)(vb >= pw3) + (int)(vb >= pw4)
            + (int)(vb >= pw5) + (int)(vb >= pw6)
            + (int)(vb >= pw7) + (int)(vb >= pw8);
    cnt += __shfl_xor_sync(FULL_MASK, cnt, 1, 4);
    cnt += __shfl_xor_sync(FULL_MASK, cnt, 2, 4);
    const int bin = min(cnt, 31);

    // ---- owner lane finalizes from its own registers ----
    if (t == (bin >> 3)) {
        const int j = bin & 7;
        const bool b1 = (j & 1), b2 = (j & 2), b4 = (j & 4);
        // local exclusive prefixes at j (pw0 = pa0 = 0)
        const float pwj = b4 ? (b2 ? (b1 ? pw7 : pw6) : (b1 ? pw5 : pw4))
                             : (b2 ? (b1 ? pw3 : pw2) : (b1 ? pw1 : 0.0f));
        const float paj = b4 ? (b2 ? (b1 ? pa7 : pa6) : (b1 ? pa5 : pa4))
                             : (b2 ? (b1 ? pa3 : pa2) : (b1 ? pa1 : 0.0f));
        const float wj  = b4 ? (b2 ? (b1 ? wb.w : wb.z) : (b1 ? wb.y : wb.x))
                             : (b2 ? (b1 ? wa.w : wa.z) : (b1 ? wa.y : wa.x));
        const float vj  = b4 ? (b2 ? (b1 ? v7 : v6) : (b1 ? v5 : v4))
                             : (b2 ? (b1 ? v3 : v2) : (b1 ? v1 : v0));
        const float vj1 = b4 ? (b2 ? (b1 ? v8 : v7) : (b1 ? v6 : v5))
                             : (b2 ? (b1 ? v4 : v3) : (b1 ? v2 : v1));

        const float edge_b = bw + pwj;
        const float alpha  = __fdividef(val - edge_b, wj + 1e-8f);
        const float dv     = vj1 - vj;
        const float z      = (ba + paj) + alpha * wj * (vj + 0.5f * alpha * dv);
        out[row]     = z;
        out[n + row] = __logf(vj + alpha * dv + 1e-8f);
    }
}

extern "C" void kernel_launch(void* const* d_in, const int* in_sizes, int n_in,
                              void* d_out, int out_size)
{
    const float* x_b = (const float*)d_in[0];
    const float* W   = (const float*)d_in[1];
    const float* V   = (const float*)d_in[2];
    float* out = (float*)d_out;

    const int n = in_sizes[0];
    const int rowsPerBlock = 64;               // 8 warps * 8 rows
    const int blocks = (n + rowsPerBlock - 1) / rowsPerBlock;
    pwq_coupling_kernel<<<blocks, 256>>>(x_b, W, V, out, n);
}